// round 2
// baseline (speedup 1.0000x reference)
#include <cuda_runtime.h>
#include <math.h>

#define BATCH 4
#define N1V 2048
#define N2V 2048
#define DIMV 512
#define NHEAD 8
#define HD 64

// Scratch (device globals: no allocation allowed in kernel_launch)
__device__ __align__(256) float g_Q   [BATCH * N1V * DIMV];
__device__ __align__(256) float g_K   [BATCH * N2V * DIMV];
__device__ __align__(256) float g_V   [BATCH * N2V * DIMV];
__device__ __align__(256) float g_W2  [BATCH * N1V * DIMV];   // g1 @ W
__device__ __align__(256) float g_CTX [BATCH * N1V * DIMV];   // attention context
__device__ __align__(256) float g_CTXO[BATCH * N1V * DIMV];   // context @ Wo^T + bo

// ---------------------------------------------------------------------------
// C[M][N] = A[M][K] @ B (+ bias).  TRANSB: B[k][n] = Wt[n][k] (torch Linear).
//           else:                  B[k][n] = Wt[k][n].
// 128x128 tile, BK=8, 256 threads, 8x8 microtile per thread.
// ---------------------------------------------------------------------------
template<bool TRANSB, bool HASBIAS>
__global__ __launch_bounds__(256) void gemm128(
    const float* __restrict__ A, const float* __restrict__ Wt,
    const float* __restrict__ bias, float* __restrict__ C,
    int M, int N, int K)
{
    __shared__ float As[8][128];
    __shared__ float Bs[8][132];

    const int t  = threadIdx.x;
    const int tx = t & 15, ty = t >> 4;
    const int m0 = blockIdx.y * 128, n0 = blockIdx.x * 128;

    float acc[8][8];
#pragma unroll
    for (int i = 0; i < 8; i++)
#pragma unroll
        for (int j = 0; j < 8; j++) acc[i][j] = 0.f;

    const int lrow = t >> 1;          // 0..127
    const int lk4  = (t & 1) * 4;     // 0 or 4

    for (int k0 = 0; k0 < K; k0 += 8) {
        float4 av = *(const float4*)(A + (m0 + lrow) * K + k0 + lk4);
        As[lk4 + 0][lrow] = av.x;
        As[lk4 + 1][lrow] = av.y;
        As[lk4 + 2][lrow] = av.z;
        As[lk4 + 3][lrow] = av.w;
        if (TRANSB) {
            float4 bv = *(const float4*)(Wt + (n0 + lrow) * K + k0 + lk4);
            Bs[lk4 + 0][lrow] = bv.x;
            Bs[lk4 + 1][lrow] = bv.y;
            Bs[lk4 + 2][lrow] = bv.z;
            Bs[lk4 + 3][lrow] = bv.w;
        } else {
            const int kk = t >> 5;          // 0..7
            const int nn = (t & 31) * 4;    // 0..124
            float4 bv = *(const float4*)(Wt + (k0 + kk) * N + n0 + nn);
            Bs[kk][nn + 0] = bv.x;
            Bs[kk][nn + 1] = bv.y;
            Bs[kk][nn + 2] = bv.z;
            Bs[kk][nn + 3] = bv.w;
        }
        __syncthreads();
#pragma unroll
        for (int k = 0; k < 8; k++) {
            float a[8], b[8];
#pragma unroll
            for (int i = 0; i < 8; i++) a[i] = As[k][ty * 8 + i];
#pragma unroll
            for (int j = 0; j < 8; j++) b[j] = Bs[k][tx * 8 + j];
#pragma unroll
            for (int i = 0; i < 8; i++)
#pragma unroll
                for (int j = 0; j < 8; j++)
                    acc[i][j] += a[i] * b[j];
        }
        __syncthreads();
    }

#pragma unroll
    for (int i = 0; i < 8; i++) {
        const int row = m0 + ty * 8 + i;
#pragma unroll
        for (int j = 0; j < 8; j++) {
            const int col = n0 + tx * 8 + j;
            float v = acc[i][j];
            if (HASBIAS) v += bias[col];
            C[row * N + col] = v;
        }
    }
}

// ---------------------------------------------------------------------------
// Flash attention, fp32. One block = (64 q-rows) x (one b,h). BK=32 tiles.
// 8 warps; warp w owns q-rows w*8..w*8+7.
// Ks row stride = 66 floats: even (float2-aligned), 2-way bank conflict only.
// ---------------------------------------------------------------------------
#define KS_STRIDE 66

__global__ __launch_bounds__(256) void attn_kernel(
    const float* __restrict__ Q, const float* __restrict__ K,
    const float* __restrict__ V, float* __restrict__ ctx)
{
    __shared__ float Qs[64 * 64];            // 16 KB
    __shared__ float Ks[32 * KS_STRIDE];     //  8.25 KB
    __shared__ float Vs[32 * 64];            //  8 KB
    __shared__ float Ps[8 * 8 * 32];         //  8 KB  [warp][row][k]

    const int qb = blockIdx.x;           // 0..31
    const int bh = blockIdx.y;           // 0..31
    const int b  = bh >> 3, h = bh & 7;
    const int t  = threadIdx.x;
    const int w  = t >> 5, lane = t & 31;

    const float* Qb = Q + (b * N1V + qb * 64) * DIMV + h * HD;
    const float* Kb = K + (b * N2V) * DIMV + h * HD;
    const float* Vb = V + (b * N2V) * DIMV + h * HD;

    for (int i = t; i < 64 * 16; i += 256) {
        const int row = i >> 4, c4 = (i & 15) << 2;
        float4 v = *(const float4*)(Qb + row * DIMV + c4);
        *(float4*)&Qs[row * 64 + c4] = v;
    }

    float m_[8], l_[8], O0[8], O1[8];
#pragma unroll
    for (int r = 0; r < 8; r++) { m_[r] = -1e30f; l_[r] = 0.f; O0[r] = 0.f; O1[r] = 0.f; }

    const int r0 = w * 8;

    for (int kt = 0; kt < N2V / 32; kt++) {
        __syncthreads();   // previous tile's compute done before overwrite
        const float* Kp = Kb + kt * 32 * DIMV;
        const float* Vp = Vb + kt * 32 * DIMV;
        for (int i = t; i < 32 * 16; i += 256) {
            const int row = i >> 4, c4 = (i & 15) << 2;
            float4 v = *(const float4*)(Kp + row * DIMV + c4);
            Ks[row * KS_STRIDE + c4 + 0] = v.x;
            Ks[row * KS_STRIDE + c4 + 1] = v.y;
            Ks[row * KS_STRIDE + c4 + 2] = v.z;
            Ks[row * KS_STRIDE + c4 + 3] = v.w;
            float4 u = *(const float4*)(Vp + row * DIMV + c4);
            *(float4*)&Vs[row * 64 + c4] = u;
        }
        __syncthreads();

        // S[r][lane] = dot(Q[r], K[lane]) over hd=64
        float s[8];
#pragma unroll
        for (int r = 0; r < 8; r++) s[r] = 0.f;
#pragma unroll 8
        for (int d = 0; d < 64; d += 2) {
            float2 kk = *(const float2*)&Ks[lane * KS_STRIDE + d];
#pragma unroll
            for (int rr = 0; rr < 8; rr++) {
                float2 q = *(const float2*)&Qs[(r0 + rr) * 64 + d];
                s[rr] += q.x * kk.x + q.y * kk.y;
            }
        }

        // online softmax per row
#pragma unroll
        for (int rr = 0; rr < 8; rr++) {
            float sv = s[rr] * 0.125f;   // 1/sqrt(64)
            float mx = sv;
#pragma unroll
            for (int off = 16; off; off >>= 1)
                mx = fmaxf(mx, __shfl_xor_sync(0xffffffffu, mx, off));
            const float mnew = fmaxf(m_[rr], mx);
            const float p = __expf(sv - mnew);
            float ps = p;
#pragma unroll
            for (int off = 16; off; off >>= 1)
                ps += __shfl_xor_sync(0xffffffffu, ps, off);
            const float alpha = __expf(m_[rr] - mnew);
            m_[rr] = mnew;
            l_[rr] = l_[rr] * alpha + ps;
            O0[rr] *= alpha;
            O1[rr] *= alpha;
            Ps[(w * 8 + rr) * 32 + lane] = p;
        }
        __syncwarp();

        // O[r][2*lane..2*lane+1] += P[r][:] @ V[:, 2*lane..2*lane+1]
#pragma unroll 4
        for (int k = 0; k < 32; k++) {
            float2 v = *(const float2*)&Vs[k * 64 + 2 * lane];
#pragma unroll
            for (int rr = 0; rr < 8; rr++) {
                const float p = Ps[(w * 8 + rr) * 32 + k];
                O0[rr] += p * v.x;
                O1[rr] += p * v.y;
            }
        }
        __syncwarp();   // all lanes done reading Ps before next tile overwrites
    }

#pragma unroll
    for (int rr = 0; rr < 8; rr++) {
        const float inv = 1.0f / l_[rr];
        float2 o;
        o.x = O0[rr] * inv;
        o.y = O1[rr] * inv;
        const int row = qb * 64 + r0 + rr;
        *(float2*)(ctx + (b * N1V + row) * DIMV + h * HD + 2 * lane) = o;
    }
}

// ---------------------------------------------------------------------------
// out[row] = softplus( dot(weighted[row], ctxO[row]) * scale )
// ---------------------------------------------------------------------------
__global__ __launch_bounds__(128) void score_kernel(
    const float* __restrict__ A, const float* __restrict__ Bc,
    const float* __restrict__ scale, float* __restrict__ out)
{
    const int row = blockIdx.x;
    const int t = threadIdx.x;
    const float4* a = (const float4*)(A + row * DIMV);
    const float4* b = (const float4*)(Bc + row * DIMV);
    const float4 x = a[t];
    const float4 y = b[t];
    float s = x.x * y.x + x.y * y.y + x.z * y.z + x.w * y.w;
#pragma unroll
    for (int off = 16; off; off >>= 1)
        s += __shfl_xor_sync(0xffffffffu, s, off);
    __shared__ float red[4];
    if ((t & 31) == 0) red[t >> 5] = s;
    __syncthreads();
    if (t == 0) {
        const float tot = red[0] + red[1] + red[2] + red[3];
        const float z = tot * scale[0];
        out[row] = fmaxf(z, 0.f) + log1pf(__expf(-fabsf(z)));
    }
}

// ---------------------------------------------------------------------------
extern "C" void kernel_launch(void* const* d_in, const int* in_sizes, int n_in,
                              void* d_out, int out_size)
{
    const float* g1    = (const float*)d_in[0];
    const float* g2    = (const float*)d_in[1];
    const float* Wq    = (const float*)d_in[2];
    const float* bq    = (const float*)d_in[3];
    const float* Wk    = (const float*)d_in[4];
    const float* bk    = (const float*)d_in[5];
    const float* Wv    = (const float*)d_in[6];
    const float* bv    = (const float*)d_in[7];
    const float* Wo    = (const float*)d_in[8];
    const float* bo    = (const float*)d_in[9];
    const float* Wb    = (const float*)d_in[10];
    const float* scale = (const float*)d_in[11];
    float* out = (float*)d_out;

    float *Qp, *Kp, *Vp, *W2p, *CTXp, *CTXOp;
    cudaGetSymbolAddress((void**)&Qp,    g_Q);
    cudaGetSymbolAddress((void**)&Kp,    g_K);
    cudaGetSymbolAddress((void**)&Vp,    g_V);
    cudaGetSymbolAddress((void**)&W2p,   g_W2);
    cudaGetSymbolAddress((void**)&CTXp,  g_CTX);
    cudaGetSymbolAddress((void**)&CTXOp, g_CTXO);

    const int M = BATCH * N1V;                 // 8192
    dim3 gg(DIMV / 128, M / 128);              // (4, 64)

    gemm128<true,  true ><<<gg, 256>>>(g1,   Wq, bq,      Qp,    M, DIMV, DIMV);
    gemm128<true,  true ><<<gg, 256>>>(g2,   Wk, bk,      Kp,    M, DIMV, DIMV);
    gemm128<true,  true ><<<gg, 256>>>(g2,   Wv, bv,      Vp,    M, DIMV, DIMV);
    gemm128<false, false><<<gg, 256>>>(g1,   Wb, nullptr, W2p,   M, DIMV, DIMV);

    attn_kernel<<<dim3(N1V / 64, BATCH * NHEAD), 256>>>(Qp, Kp, Vp, CTXp);

    gemm128<true,  true ><<<gg, 256>>>(CTXp, Wo, bo,      CTXOp, M, DIMV, DIMV);

    score_kernel<<<M, 128>>>(W2p, CTXOp, scale, out);
}

// round 3
// speedup vs baseline: 3.8816x; 3.8816x over previous
#include <cuda_runtime.h>
#include <math.h>
#include <stdint.h>

#define BATCH 4
#define N1V 2048
#define N2V 2048
#define DIMV 512
#define NHEAD 8
#define HD 64

// Scratch (device globals: no allocation allowed in kernel_launch)
__device__ __align__(256) float g_Q   [BATCH * N1V * DIMV];
__device__ __align__(256) float g_K   [BATCH * N2V * DIMV];
__device__ __align__(256) float g_V   [BATCH * N2V * DIMV];
__device__ __align__(256) float g_W2  [BATCH * N1V * DIMV];
__device__ __align__(256) float g_CTX [BATCH * N1V * DIMV];
__device__ __align__(256) float g_CTXO[BATCH * N1V * DIMV];

// ---------------------------------------------------------------------------
__device__ __forceinline__ uint32_t f2tf(float x) {
    uint32_t u;
    asm("cvt.rna.tf32.f32 %0, %1;" : "=r"(u) : "f"(x));
    return u;
}

__device__ __forceinline__ void mma_tf32(float* c, const uint32_t* a, const uint32_t* b) {
    asm volatile(
        "mma.sync.aligned.m16n8k8.row.col.f32.tf32.tf32.f32 "
        "{%0,%1,%2,%3}, {%4,%5,%6,%7}, {%8,%9}, {%0,%1,%2,%3};\n"
        : "+f"(c[0]), "+f"(c[1]), "+f"(c[2]), "+f"(c[3])
        : "r"(a[0]), "r"(a[1]), "r"(a[2]), "r"(a[3]), "r"(b[0]), "r"(b[1]));
}

// ---------------------------------------------------------------------------
// tf32 tensor-core GEMM: C[M][N] = A[M][K] @ B (+bias)
// TRANSB: B[k][n] = Wt[n][k] (torch Linear weight). else B[k][n] = Wt[k][n].
// 128x128 block, BK=32, 256 threads (8 warps, 2x4), warp tile 64x32.
// ---------------------------------------------------------------------------
#define AS_STRIDE 36
#define BS_STRIDE_NT 132

template<bool TRANSB, bool HASBIAS>
__global__ __launch_bounds__(256) void gemm_tc(
    const float* __restrict__ A, const float* __restrict__ Wt,
    const float* __restrict__ bias, float* __restrict__ C,
    int M, int N, int K)
{
    __shared__ uint32_t As[128 * AS_STRIDE];
    __shared__ uint32_t Bs[128 * AS_STRIDE];   // large enough for both layouts

    const int t    = threadIdx.x;
    const int w    = t >> 5;
    const int lane = t & 31;
    const int g    = lane >> 2;
    const int tid4 = lane & 3;
    const int m0   = blockIdx.y * 128, n0 = blockIdx.x * 128;
    const int warpM = (w >> 2) * 64;           // 0 or 64
    const int warpN = (w & 3) * 32;            // 0,32,64,96

    float acc[4][4][4];
#pragma unroll
    for (int mi = 0; mi < 4; mi++)
#pragma unroll
        for (int ni = 0; ni < 4; ni++)
#pragma unroll
            for (int c = 0; c < 4; c++) acc[mi][ni][c] = 0.f;

    for (int k0 = 0; k0 < K; k0 += 32) {
        __syncthreads();
        // A tile: 128 rows x 32 k
#pragma unroll
        for (int j = 0; j < 4; j++) {
            const int idx = t + 256 * j;
            const int row = idx >> 3, c4 = (idx & 7) << 2;
            float4 v = *(const float4*)(A + (size_t)(m0 + row) * K + k0 + c4);
            uint32_t* p = &As[row * AS_STRIDE + c4];
            p[0] = f2tf(v.x); p[1] = f2tf(v.y); p[2] = f2tf(v.z); p[3] = f2tf(v.w);
        }
        if (TRANSB) {
            // Wt[n][k] -> Bs[n][k] (same layout as A)
#pragma unroll
            for (int j = 0; j < 4; j++) {
                const int idx = t + 256 * j;
                const int row = idx >> 3, c4 = (idx & 7) << 2;
                float4 v = *(const float4*)(Wt + (size_t)(n0 + row) * K + k0 + c4);
                uint32_t* p = &Bs[row * AS_STRIDE + c4];
                p[0] = f2tf(v.x); p[1] = f2tf(v.y); p[2] = f2tf(v.z); p[3] = f2tf(v.w);
            }
        } else {
            // W[k][n] -> Bs[k][n], stride 132
#pragma unroll
            for (int j = 0; j < 4; j++) {
                const int idx = t + 256 * j;
                const int row = idx >> 5, n4 = (idx & 31) << 2;
                float4 v = *(const float4*)(Wt + (size_t)(k0 + row) * N + n0 + n4);
                uint32_t* p = &Bs[row * BS_STRIDE_NT + n4];
                p[0] = f2tf(v.x); p[1] = f2tf(v.y); p[2] = f2tf(v.z); p[3] = f2tf(v.w);
            }
        }
        __syncthreads();

#pragma unroll
        for (int ks = 0; ks < 4; ks++) {
            uint32_t a[4][4], b[4][2];
            const int kc = tid4 + 8 * ks;
#pragma unroll
            for (int mi = 0; mi < 4; mi++) {
                const int r = warpM + 16 * mi + g;
                a[mi][0] = As[r * AS_STRIDE + kc];
                a[mi][1] = As[(r + 8) * AS_STRIDE + kc];
                a[mi][2] = As[r * AS_STRIDE + kc + 4];
                a[mi][3] = As[(r + 8) * AS_STRIDE + kc + 4];
            }
#pragma unroll
            for (int ni = 0; ni < 4; ni++) {
                if (TRANSB) {
                    const int n = warpN + 8 * ni + g;
                    b[ni][0] = Bs[n * AS_STRIDE + kc];
                    b[ni][1] = Bs[n * AS_STRIDE + kc + 4];
                } else {
                    const int n = warpN + 8 * ni + g;
                    b[ni][0] = Bs[kc * BS_STRIDE_NT + n];
                    b[ni][1] = Bs[(kc + 4) * BS_STRIDE_NT + n];
                }
            }
#pragma unroll
            for (int mi = 0; mi < 4; mi++)
#pragma unroll
                for (int ni = 0; ni < 4; ni++)
                    mma_tf32(acc[mi][ni], a[mi], b[ni]);
        }
    }

    // epilogue
#pragma unroll
    for (int mi = 0; mi < 4; mi++) {
#pragma unroll
        for (int ni = 0; ni < 4; ni++) {
            const int row = m0 + warpM + 16 * mi + g;
            const int col = n0 + warpN + 8 * ni + 2 * tid4;
            float bx = 0.f, by = 0.f;
            if (HASBIAS) { bx = bias[col]; by = bias[col + 1]; }
            float2 v0 = make_float2(acc[mi][ni][0] + bx, acc[mi][ni][1] + by);
            float2 v1 = make_float2(acc[mi][ni][2] + bx, acc[mi][ni][3] + by);
            *(float2*)(C + (size_t)row * N + col)       = v0;
            *(float2*)(C + (size_t)(row + 8) * N + col) = v1;
        }
    }
}

// ---------------------------------------------------------------------------
// Flash attention, tf32 tensor cores.
// Block = 128 q-rows x one (b,h). 4 warps, warp tile 32 q-rows. BK=64.
// Dynamic smem: Qs[128][68] | Ks[64][68] | Vs[64][68] | Ps[128][68] (tf32 bits)
// ---------------------------------------------------------------------------
#define BQ 128
#define BKV 64
#define AT_STRIDE 68
#define ATTN_SMEM ((BQ + BKV + BKV + BQ) * AT_STRIDE * 4)

__global__ __launch_bounds__(128) void attn_tc(
    const float* __restrict__ Q, const float* __restrict__ K,
    const float* __restrict__ V, float* __restrict__ ctx)
{
    extern __shared__ uint32_t sm[];
    uint32_t* Qs = sm;
    uint32_t* Ks = Qs + BQ * AT_STRIDE;
    uint32_t* Vs = Ks + BKV * AT_STRIDE;
    uint32_t* Ps = Vs + BKV * AT_STRIDE;

    const int qb = blockIdx.x;
    const int bh = blockIdx.y;
    const int b  = bh >> 3, h = bh & 7;
    const int t  = threadIdx.x;
    const int w  = t >> 5, lane = t & 31;
    const int g  = lane >> 2, tid4 = lane & 3;

    const float* Qb = Q + ((size_t)b * N1V + qb * BQ) * DIMV + h * HD;
    const float* Kb = K + (size_t)b * N2V * DIMV + h * HD;
    const float* Vb = V + (size_t)b * N2V * DIMV + h * HD;

    // load Q tile (128x64)
#pragma unroll
    for (int j = 0; j < 16; j++) {
        const int idx = t + 128 * j;
        const int row = idx >> 4, c4 = (idx & 15) << 2;
        float4 v = *(const float4*)(Qb + (size_t)row * DIMV + c4);
        uint32_t* p = &Qs[row * AT_STRIDE + c4];
        p[0] = f2tf(v.x); p[1] = f2tf(v.y); p[2] = f2tf(v.z); p[3] = f2tf(v.w);
    }

    float m_[2][2], l_[2][2], o[2][8][4];
#pragma unroll
    for (int mi = 0; mi < 2; mi++) {
        m_[mi][0] = -1e30f; m_[mi][1] = -1e30f;
        l_[mi][0] = 0.f;    l_[mi][1] = 0.f;
#pragma unroll
        for (int ni = 0; ni < 8; ni++)
#pragma unroll
            for (int c = 0; c < 4; c++) o[mi][ni][c] = 0.f;
    }

    for (int kt = 0; kt < N2V / BKV; kt++) {
        __syncthreads();
        // load K,V tiles (64x64 each)
#pragma unroll
        for (int j = 0; j < 8; j++) {
            const int idx = t + 128 * j;
            const int row = idx >> 4, c4 = (idx & 15) << 2;
            float4 kv = *(const float4*)(Kb + (size_t)(kt * BKV + row) * DIMV + c4);
            uint32_t* pk = &Ks[row * AT_STRIDE + c4];
            pk[0] = f2tf(kv.x); pk[1] = f2tf(kv.y); pk[2] = f2tf(kv.z); pk[3] = f2tf(kv.w);
            float4 vv = *(const float4*)(Vb + (size_t)(kt * BKV + row) * DIMV + c4);
            uint32_t* pv = &Vs[row * AT_STRIDE + c4];
            pv[0] = f2tf(vv.x); pv[1] = f2tf(vv.y); pv[2] = f2tf(vv.z); pv[3] = f2tf(vv.w);
        }
        __syncthreads();

        // S = Q @ K^T  (warp: 32 rows x 64 cols)
        float s[2][8][4];
#pragma unroll
        for (int mi = 0; mi < 2; mi++)
#pragma unroll
            for (int ni = 0; ni < 8; ni++)
#pragma unroll
                for (int c = 0; c < 4; c++) s[mi][ni][c] = 0.f;

#pragma unroll
        for (int ks = 0; ks < 8; ks++) {
            const int kc = tid4 + 8 * ks;
            uint32_t a[2][4], bf[8][2];
#pragma unroll
            for (int mi = 0; mi < 2; mi++) {
                const int r = w * 32 + 16 * mi + g;
                a[mi][0] = Qs[r * AT_STRIDE + kc];
                a[mi][1] = Qs[(r + 8) * AT_STRIDE + kc];
                a[mi][2] = Qs[r * AT_STRIDE + kc + 4];
                a[mi][3] = Qs[(r + 8) * AT_STRIDE + kc + 4];
            }
#pragma unroll
            for (int ni = 0; ni < 8; ni++) {
                const int n = 8 * ni + g;
                bf[ni][0] = Ks[n * AT_STRIDE + kc];
                bf[ni][1] = Ks[n * AT_STRIDE + kc + 4];
            }
#pragma unroll
            for (int mi = 0; mi < 2; mi++)
#pragma unroll
                for (int ni = 0; ni < 8; ni++)
                    mma_tf32(s[mi][ni], a[mi], bf[ni]);
        }

        // online softmax; write P (tf32) to per-warp Ps region
#pragma unroll
        for (int mi = 0; mi < 2; mi++) {
            float mx0 = -1e30f, mx1 = -1e30f;
#pragma unroll
            for (int ni = 0; ni < 8; ni++) {
#pragma unroll
                for (int c = 0; c < 4; c++) s[mi][ni][c] *= 0.125f;  // 1/sqrt(64)
                mx0 = fmaxf(mx0, fmaxf(s[mi][ni][0], s[mi][ni][1]));
                mx1 = fmaxf(mx1, fmaxf(s[mi][ni][2], s[mi][ni][3]));
            }
            mx0 = fmaxf(mx0, __shfl_xor_sync(0xffffffffu, mx0, 1));
            mx0 = fmaxf(mx0, __shfl_xor_sync(0xffffffffu, mx0, 2));
            mx1 = fmaxf(mx1, __shfl_xor_sync(0xffffffffu, mx1, 1));
            mx1 = fmaxf(mx1, __shfl_xor_sync(0xffffffffu, mx1, 2));
            const float mn0 = fmaxf(m_[mi][0], mx0);
            const float mn1 = fmaxf(m_[mi][1], mx1);
            float sum0 = 0.f, sum1 = 0.f;
#pragma unroll
            for (int ni = 0; ni < 8; ni++) {
                s[mi][ni][0] = __expf(s[mi][ni][0] - mn0);
                s[mi][ni][1] = __expf(s[mi][ni][1] - mn0);
                s[mi][ni][2] = __expf(s[mi][ni][2] - mn1);
                s[mi][ni][3] = __expf(s[mi][ni][3] - mn1);
                sum0 += s[mi][ni][0] + s[mi][ni][1];
                sum1 += s[mi][ni][2] + s[mi][ni][3];
            }
            sum0 += __shfl_xor_sync(0xffffffffu, sum0, 1);
            sum0 += __shfl_xor_sync(0xffffffffu, sum0, 2);
            sum1 += __shfl_xor_sync(0xffffffffu, sum1, 1);
            sum1 += __shfl_xor_sync(0xffffffffu, sum1, 2);
            const float al0 = __expf(m_[mi][0] - mn0);
            const float al1 = __expf(m_[mi][1] - mn1);
            m_[mi][0] = mn0; m_[mi][1] = mn1;
            l_[mi][0] = l_[mi][0] * al0 + sum0;
            l_[mi][1] = l_[mi][1] * al1 + sum1;
#pragma unroll
            for (int ni = 0; ni < 8; ni++) {
                o[mi][ni][0] *= al0; o[mi][ni][1] *= al0;
                o[mi][ni][2] *= al1; o[mi][ni][3] *= al1;
            }
            const int r = w * 32 + 16 * mi + g;
#pragma unroll
            for (int ni = 0; ni < 8; ni++) {
                const int col = 2 * tid4 + 8 * ni;
                Ps[r * AT_STRIDE + col]           = f2tf(s[mi][ni][0]);
                Ps[r * AT_STRIDE + col + 1]       = f2tf(s[mi][ni][1]);
                Ps[(r + 8) * AT_STRIDE + col]     = f2tf(s[mi][ni][2]);
                Ps[(r + 8) * AT_STRIDE + col + 1] = f2tf(s[mi][ni][3]);
            }
        }
        __syncwarp();

        // O += P @ V
#pragma unroll
        for (int ks = 0; ks < 8; ks++) {
            const int kc = tid4 + 8 * ks;
            uint32_t a[2][4], bf[8][2];
#pragma unroll
            for (int mi = 0; mi < 2; mi++) {
                const int r = w * 32 + 16 * mi + g;
                a[mi][0] = Ps[r * AT_STRIDE + kc];
                a[mi][1] = Ps[(r + 8) * AT_STRIDE + kc];
                a[mi][2] = Ps[r * AT_STRIDE + kc + 4];
                a[mi][3] = Ps[(r + 8) * AT_STRIDE + kc + 4];
            }
#pragma unroll
            for (int ni = 0; ni < 8; ni++) {
                const int n = 8 * ni + g;
                bf[ni][0] = Vs[kc * AT_STRIDE + n];
                bf[ni][1] = Vs[(kc + 4) * AT_STRIDE + n];
            }
#pragma unroll
            for (int mi = 0; mi < 2; mi++)
#pragma unroll
                for (int ni = 0; ni < 8; ni++)
                    mma_tf32(o[mi][ni], a[mi], bf[ni]);
        }
    }

    // write context
#pragma unroll
    for (int mi = 0; mi < 2; mi++) {
        const float inv0 = 1.0f / l_[mi][0];
        const float inv1 = 1.0f / l_[mi][1];
        const int r = qb * BQ + w * 32 + 16 * mi + g;
#pragma unroll
        for (int ni = 0; ni < 8; ni++) {
            const int col = h * HD + 2 * tid4 + 8 * ni;
            float2 v0 = make_float2(o[mi][ni][0] * inv0, o[mi][ni][1] * inv0);
            float2 v1 = make_float2(o[mi][ni][2] * inv1, o[mi][ni][3] * inv1);
            *(float2*)(ctx + ((size_t)b * N1V + r) * DIMV + col)     = v0;
            *(float2*)(ctx + ((size_t)b * N1V + r + 8) * DIMV + col) = v1;
        }
    }
}

// ---------------------------------------------------------------------------
__global__ __launch_bounds__(128) void score_kernel(
    const float* __restrict__ A, const float* __restrict__ Bc,
    const float* __restrict__ scale, float* __restrict__ out)
{
    const int row = blockIdx.x;
    const int t = threadIdx.x;
    const float4 x = ((const float4*)(A + (size_t)row * DIMV))[t];
    const float4 y = ((const float4*)(Bc + (size_t)row * DIMV))[t];
    float s = x.x * y.x + x.y * y.y + x.z * y.z + x.w * y.w;
#pragma unroll
    for (int off = 16; off; off >>= 1)
        s += __shfl_xor_sync(0xffffffffu, s, off);
    __shared__ float red[4];
    if ((t & 31) == 0) red[t >> 5] = s;
    __syncthreads();
    if (t == 0) {
        const float tot = red[0] + red[1] + red[2] + red[3];
        const float z = tot * scale[0];
        out[row] = fmaxf(z, 0.f) + log1pf(__expf(-fabsf(z)));
    }
}

// ---------------------------------------------------------------------------
extern "C" void kernel_launch(void* const* d_in, const int* in_sizes, int n_in,
                              void* d_out, int out_size)
{
    const float* g1    = (const float*)d_in[0];
    const float* g2    = (const float*)d_in[1];
    const float* Wq    = (const float*)d_in[2];
    const float* bq    = (const float*)d_in[3];
    const float* Wk    = (const float*)d_in[4];
    const float* bk    = (const float*)d_in[5];
    const float* Wv    = (const float*)d_in[6];
    const float* bv    = (const float*)d_in[7];
    const float* Wo    = (const float*)d_in[8];
    const float* bo    = (const float*)d_in[9];
    const float* Wb    = (const float*)d_in[10];
    const float* scale = (const float*)d_in[11];
    float* out = (float*)d_out;

    float *Qp, *Kp, *Vp, *W2p, *CTXp, *CTXOp;
    cudaGetSymbolAddress((void**)&Qp,    g_Q);
    cudaGetSymbolAddress((void**)&Kp,    g_K);
    cudaGetSymbolAddress((void**)&Vp,    g_V);
    cudaGetSymbolAddress((void**)&W2p,   g_W2);
    cudaGetSymbolAddress((void**)&CTXp,  g_CTX);
    cudaGetSymbolAddress((void**)&CTXOp, g_CTXO);

    cudaFuncSetAttribute(attn_tc, cudaFuncAttributeMaxDynamicSharedMemorySize, ATTN_SMEM);

    const int M = BATCH * N1V;                 // 8192
    dim3 gg(DIMV / 128, M / 128);              // (4, 64)

    gemm_tc<true,  true ><<<gg, 256>>>(g1,   Wq, bq,      Qp,    M, DIMV, DIMV);
    gemm_tc<true,  true ><<<gg, 256>>>(g2,   Wk, bk,      Kp,    M, DIMV, DIMV);
    gemm_tc<true,  true ><<<gg, 256>>>(g2,   Wv, bv,      Vp,    M, DIMV, DIMV);
    gemm_tc<false, false><<<gg, 256>>>(g1,   Wb, nullptr, W2p,   M, DIMV, DIMV);

    attn_tc<<<dim3(N1V / BQ, BATCH * NHEAD), 128, ATTN_SMEM>>>(Qp, Kp, Vp, CTXp);

    gemm_tc<true,  true ><<<gg, 256>>>(CTXp, Wo, bo,      CTXOp, M, DIMV, DIMV);

    score_kernel<<<M, 128>>>(W2p, CTXOp, scale, out);
}